// round 1
// baseline (speedup 1.0000x reference)
#include <cuda_runtime.h>
#include <math.h>

#define NCLUST 196
#define DIM 256
#define NROWS 262144
#define TEMP_INV 2.0f        // 1/TEMPERATURE
#define EPSV 1e-12f

// -------- scratch (device globals; no allocation allowed) --------
__device__ float g_sums[2][NCLUST * DIM];     // [q,k] segment sums
__device__ float g_centers[2][NCLUST * DIM];  // normalized centers
__device__ int   g_counts[NCLUST];
__device__ int   g_cursor[NCLUST];
__device__ int   g_perm[NROWS];               // row indices sorted by label
__device__ int   g_plab[NROWS];               // label of perm[i] (sorted labels)
__device__ float g_loss[NCLUST];

// -------- 1. zero scratch --------
__global__ void k_zero() {
    int i = blockIdx.x * blockDim.x + threadIdx.x;
    int stride = gridDim.x * blockDim.x;
    float* s = &g_sums[0][0];
    for (int k = i; k < 2 * NCLUST * DIM; k += stride) s[k] = 0.0f;
    for (int k = i; k < NCLUST; k += stride) g_counts[k] = 0;
}

// -------- 2. histogram of labels --------
__global__ void k_hist(const int* __restrict__ labels) {
    __shared__ int s_cnt[NCLUST];
    for (int i = threadIdx.x; i < NCLUST; i += blockDim.x) s_cnt[i] = 0;
    __syncthreads();
    for (int r = blockIdx.x * blockDim.x + threadIdx.x; r < NROWS;
         r += gridDim.x * blockDim.x)
        atomicAdd(&s_cnt[labels[r]], 1);
    __syncthreads();
    for (int i = threadIdx.x; i < NCLUST; i += blockDim.x)
        if (s_cnt[i]) atomicAdd(&g_counts[i], s_cnt[i]);
}

// -------- 3. exclusive prefix scan -> cursor (start offsets) --------
__global__ void k_scan() {
    if (threadIdx.x == 0) {
        int acc = 0;
        for (int c = 0; c < NCLUST; c++) {
            g_cursor[c] = acc;
            acc += g_counts[c];
        }
    }
}

// -------- 4. scatter row indices into label-sorted order --------
// grid 128 blocks x 256 thr, each block owns 2048 contiguous rows.
__global__ void k_scatter(const int* __restrict__ labels) {
    __shared__ int s_hist[NCLUST];
    __shared__ int s_base[NCLUST];
    __shared__ int s_cur[NCLUST];
    int tid = threadIdx.x;
    for (int i = tid; i < NCLUST; i += 256) { s_hist[i] = 0; s_cur[i] = 0; }
    __syncthreads();
    int r0 = blockIdx.x * 2048;
#pragma unroll
    for (int u = 0; u < 8; u++) {
        int r = r0 + u * 256 + tid;
        atomicAdd(&s_hist[labels[r]], 1);
    }
    __syncthreads();
    for (int i = tid; i < NCLUST; i += 256)
        s_base[i] = atomicAdd(&g_cursor[i], s_hist[i]);
    __syncthreads();
#pragma unroll
    for (int u = 0; u < 8; u++) {
        int r = r0 + u * 256 + tid;
        int c = labels[r];
        int p = s_base[c] + atomicAdd(&s_cur[c], 1);
        g_perm[p] = r;
        g_plab[p] = c;
    }
}

// -------- 5. segment sums over label-sorted rows (hot kernel) --------
// grid (1024, 2): x = 256-row chunk of perm, y = matrix (0=q, 1=k).
// One dim per thread; register accumulator; flush on cluster boundary.
__global__ void __launch_bounds__(256) k_segsum(const float* __restrict__ xq,
                                                const float* __restrict__ xk) {
    const float* __restrict__ x = blockIdx.y ? xk : xq;
    float* sums = &g_sums[blockIdx.y][0];
    const int d = threadIdx.x;
    const int start = blockIdx.x * 256;
    int cur = g_plab[start];
    float acc = 0.0f;
    for (int kb = start; kb < start + 256; kb += 8) {
        int rows[8], labs[8];
        float v[8];
#pragma unroll
        for (int u = 0; u < 8; u++) rows[u] = g_perm[kb + u];
#pragma unroll
        for (int u = 0; u < 8; u++) labs[u] = g_plab[kb + u];
#pragma unroll
        for (int u = 0; u < 8; u++) v[u] = x[rows[u] * DIM + d];
#pragma unroll
        for (int u = 0; u < 8; u++) {
            if (labs[u] != cur) {          // uniform branch across block
                atomicAdd(&sums[cur * DIM + d], acc);
                acc = 0.0f;
                cur = labs[u];
            }
            acc += v[u];
        }
    }
    atomicAdd(&sums[cur * DIM + d], acc);
}

// -------- 6. centers: mean + L2 normalize. grid (196, 2) x 256 thr --------
__global__ void k_centers() {
    int c = blockIdx.x;
    int m = blockIdx.y;
    int tid = threadIdx.x;
    int lane = tid & 31, w = tid >> 5;
    float cnt = (float)g_counts[c];
    float v = g_sums[m][c * DIM + tid] / fmaxf(cnt, EPSV);
    float t = v * v;
#pragma unroll
    for (int off = 16; off > 0; off >>= 1)
        t += __shfl_xor_sync(0xFFFFFFFFu, t, off);
    __shared__ float sr[8];
    __shared__ float s_norm;
    if (lane == 0) sr[w] = t;
    __syncthreads();
    if (tid == 0) {
        float tot = 0.0f;
        for (int i = 0; i < 8; i++) tot += sr[i];
        s_norm = sqrtf(tot);
    }
    __syncthreads();
    g_centers[m][c * DIM + tid] = v / fmaxf(s_norm, EPSV);
}

// -------- 7. per-row contrastive loss. grid 196 x 256 thr --------
__global__ void k_loss() {
    const int i = blockIdx.x;
    const int tid = threadIdx.x;
    const int lane = tid & 31, w = tid >> 5;
    __shared__ float s_qi[DIM];
    __shared__ float s_row[NCLUST + 1];   // [0..195] row, [196] = pos (d_k)
    __shared__ float s_red[8];
    __shared__ float s_mx, s_sum;

    s_qi[tid] = g_centers[0][i * DIM + tid];
    __syncthreads();

    // each warp: dots for jj = w, w+8, ...; jj==196 means dot(q_i, k_i)
    for (int jj = w; jj <= NCLUST; jj += 8) {
        const float* vec = (jj == NCLUST) ? &g_centers[1][i * DIM]
                                          : &g_centers[0][jj * DIM];
        float p = 0.0f;
#pragma unroll
        for (int m = 0; m < 8; m++)
            p += s_qi[m * 32 + lane] * vec[m * 32 + lane];
#pragma unroll
        for (int off = 16; off > 0; off >>= 1)
            p += __shfl_xor_sync(0xFFFFFFFFu, p, off);
        if (lane == 0) s_row[jj] = p * TEMP_INV;
    }
    __syncthreads();

    // mask: diag <- d_k; empty columns <- -10
    if (tid < NCLUST) {
        float r = (tid == i) ? s_row[NCLUST] : s_row[tid];
        if (g_counts[tid] == 0) r = -10.0f;
        s_row[tid] = r;
    }
    __syncthreads();

    // block max over 196
    float v = (tid < NCLUST) ? s_row[tid] : -1e30f;
#pragma unroll
    for (int off = 16; off > 0; off >>= 1)
        v = fmaxf(v, __shfl_xor_sync(0xFFFFFFFFu, v, off));
    if (lane == 0) s_red[w] = v;
    __syncthreads();
    if (tid == 0) {
        float mx = s_red[0];
        for (int k = 1; k < 8; k++) mx = fmaxf(mx, s_red[k]);
        s_mx = mx;
    }
    __syncthreads();
    float mx = s_mx;

    float e = (tid < NCLUST) ? __expf(s_row[tid] - mx) : 0.0f;
#pragma unroll
    for (int off = 16; off > 0; off >>= 1)
        e += __shfl_xor_sync(0xFFFFFFFFu, e, off);
    if (lane == 0) s_red[w] = e;
    __syncthreads();
    if (tid == 0) {
        float tot = 0.0f;
        for (int k = 0; k < 8; k++) tot += s_red[k];
        s_sum = tot;
    }
    __syncthreads();

    if (tid == 0) {
        if (g_counts[i] == 0)
            g_loss[i] = 0.0f;
        else
            g_loss[i] = -s_row[i] + mx + logf(s_sum);
    }
}

// -------- 8. final reduce: mean over non-empty clusters --------
__global__ void k_final(float* out) {
    const int tid = threadIdx.x;
    const int lane = tid & 31, w = tid >> 5;
    float v = (tid < NCLUST) ? g_loss[tid] : 0.0f;
    float z = (tid < NCLUST && g_counts[tid] == 0) ? 1.0f : 0.0f;
#pragma unroll
    for (int off = 16; off > 0; off >>= 1) {
        v += __shfl_xor_sync(0xFFFFFFFFu, v, off);
        z += __shfl_xor_sync(0xFFFFFFFFu, z, off);
    }
    __shared__ float sv[8], sz[8];
    if (lane == 0) { sv[w] = v; sz[w] = z; }
    __syncthreads();
    if (tid == 0) {
        float tv = 0.0f, tz = 0.0f;
        for (int k = 0; k < 8; k++) { tv += sv[k]; tz += sz[k]; }
        out[0] = tv / ((float)NCLUST - tz);
    }
}

extern "C" void kernel_launch(void* const* d_in, const int* in_sizes, int n_in,
                              void* d_out, int out_size) {
    const float* im_q = (const float*)d_in[0];
    const float* im_k = (const float*)d_in[1];
    const int* labels = (const int*)d_in[2];
    float* out = (float*)d_out;

    k_zero<<<64, 256>>>();
    k_hist<<<256, 256>>>(labels);
    k_scan<<<1, 32>>>();
    k_scatter<<<128, 256>>>(labels);
    dim3 g5(NROWS / 256, 2);
    k_segsum<<<g5, 256>>>(im_q, im_k);
    dim3 g6(NCLUST, 2);
    k_centers<<<g6, 256>>>();
    k_loss<<<NCLUST, 256>>>();
    k_final<<<1, 256>>>(out);
}

// round 2
// speedup vs baseline: 1.2282x; 1.2282x over previous
#include <cuda_runtime.h>
#include <math.h>

#define NCLUST 196
#define DIM 256
#define NROWS 262144
#define TEMP_INV 2.0f        // 1/TEMPERATURE
#define EPSV 1e-12f

// -------- scratch (device globals; no allocation allowed) --------
__device__ float g_sums[2][NCLUST * DIM];     // [q,k] segment sums
__device__ float g_centers[2][NCLUST * DIM];  // normalized centers
__device__ int   g_counts[NCLUST];
__device__ int   g_cursor[NCLUST];
__device__ int   g_perm[NROWS];               // row indices sorted by label
__device__ int   g_plab[NROWS];               // label of perm[i] (sorted labels)
__device__ float g_loss[NCLUST];

// -------- 1. zero scratch --------
__global__ void k_zero() {
    int i = blockIdx.x * blockDim.x + threadIdx.x;
    int stride = gridDim.x * blockDim.x;
    float* s = &g_sums[0][0];
    for (int k = i; k < 2 * NCLUST * DIM; k += stride) s[k] = 0.0f;
    for (int k = i; k < NCLUST; k += stride) g_counts[k] = 0;
}

// -------- 2. histogram of labels (int4-vectorized) --------
__global__ void k_hist(const int* __restrict__ labels) {
    __shared__ int s_cnt[NCLUST];
    for (int i = threadIdx.x; i < NCLUST; i += blockDim.x) s_cnt[i] = 0;
    __syncthreads();
    const int4* l4 = (const int4*)labels;
    for (int r = blockIdx.x * blockDim.x + threadIdx.x; r < NROWS / 4;
         r += gridDim.x * blockDim.x) {
        int4 v = l4[r];
        atomicAdd(&s_cnt[v.x], 1);
        atomicAdd(&s_cnt[v.y], 1);
        atomicAdd(&s_cnt[v.z], 1);
        atomicAdd(&s_cnt[v.w], 1);
    }
    __syncthreads();
    for (int i = threadIdx.x; i < NCLUST; i += blockDim.x)
        if (s_cnt[i]) atomicAdd(&g_counts[i], s_cnt[i]);
}

// -------- 3. exclusive prefix scan -> cursor (start offsets) --------
__global__ void k_scan() {
    if (threadIdx.x == 0) {
        int acc = 0;
        for (int c = 0; c < NCLUST; c++) {
            g_cursor[c] = acc;
            acc += g_counts[c];
        }
    }
}

// -------- 4. scatter row indices into label-sorted order --------
// grid 256 blocks x 256 thr, each block owns 1024 contiguous rows.
__global__ void k_scatter(const int* __restrict__ labels) {
    __shared__ int s_hist[NCLUST];
    __shared__ int s_base[NCLUST];
    __shared__ int s_cur[NCLUST];
    int tid = threadIdx.x;
    for (int i = tid; i < NCLUST; i += 256) { s_hist[i] = 0; s_cur[i] = 0; }
    __syncthreads();
    int r0 = blockIdx.x * 1024;
    int labs[4];
#pragma unroll
    for (int u = 0; u < 4; u++) labs[u] = labels[r0 + u * 256 + tid];
#pragma unroll
    for (int u = 0; u < 4; u++) atomicAdd(&s_hist[labs[u]], 1);
    __syncthreads();
    for (int i = tid; i < NCLUST; i += 256)
        s_base[i] = atomicAdd(&g_cursor[i], s_hist[i]);
    __syncthreads();
#pragma unroll
    for (int u = 0; u < 4; u++) {
        int c = labs[u];
        int p = s_base[c] + atomicAdd(&s_cur[c], 1);
        g_perm[p] = r0 + u * 256 + tid;
        g_plab[p] = c;
    }
}

// -------- 5. segment sums over label-sorted rows (hot kernel) --------
// grid (1024, 2): x = 256-row chunk of perm, y = matrix (0=q, 1=k).
// Thread t: dim quad 4*(t&63), row subgroup t>>6 (rows stride 4).
// float4 register accumulator; atomic flush only at cluster boundaries.
__global__ void __launch_bounds__(256) k_segsum(const float* __restrict__ xq,
                                                const float* __restrict__ xk) {
    const float* __restrict__ x = blockIdx.y ? xk : xq;
    float* sums = &g_sums[blockIdx.y][0];
    const int t = threadIdx.x;
    const int dq = (t & 63) * 4;      // dim-quad base
    const int sub = t >> 6;           // 0..3
    const int start = blockIdx.x * 256;

    int cur = g_plab[start + sub];
    float4 acc = make_float4(0.f, 0.f, 0.f, 0.f);

    for (int it = 0; it < 64; it += 8) {
        int rows[8], labs[8];
        float4 v[8];
#pragma unroll
        for (int u = 0; u < 8; u++) {
            int p = start + sub + (it + u) * 4;
            rows[u] = g_perm[p];
            labs[u] = g_plab[p];
        }
#pragma unroll
        for (int u = 0; u < 8; u++)
            v[u] = *(const float4*)&x[(size_t)rows[u] * DIM + dq];
#pragma unroll
        for (int u = 0; u < 8; u++) {
            if (labs[u] != cur) {
                float* dst = &sums[cur * DIM + dq];
                atomicAdd(dst + 0, acc.x);
                atomicAdd(dst + 1, acc.y);
                atomicAdd(dst + 2, acc.z);
                atomicAdd(dst + 3, acc.w);
                acc = make_float4(0.f, 0.f, 0.f, 0.f);
                cur = labs[u];
            }
            acc.x += v[u].x;
            acc.y += v[u].y;
            acc.z += v[u].z;
            acc.w += v[u].w;
        }
    }
    float* dst = &sums[cur * DIM + dq];
    atomicAdd(dst + 0, acc.x);
    atomicAdd(dst + 1, acc.y);
    atomicAdd(dst + 2, acc.z);
    atomicAdd(dst + 3, acc.w);
}

// -------- 6. centers: mean + L2 normalize. grid (196, 2) x 256 thr --------
__global__ void k_centers() {
    int c = blockIdx.x;
    int m = blockIdx.y;
    int tid = threadIdx.x;
    int lane = tid & 31, w = tid >> 5;
    float cnt = (float)g_counts[c];
    float v = g_sums[m][c * DIM + tid] / fmaxf(cnt, EPSV);
    float t = v * v;
#pragma unroll
    for (int off = 16; off > 0; off >>= 1)
        t += __shfl_xor_sync(0xFFFFFFFFu, t, off);
    __shared__ float sr[8];
    __shared__ float s_norm;
    if (lane == 0) sr[w] = t;
    __syncthreads();
    if (tid == 0) {
        float tot = 0.0f;
        for (int i = 0; i < 8; i++) tot += sr[i];
        s_norm = sqrtf(tot);
    }
    __syncthreads();
    g_centers[m][c * DIM + tid] = v / fmaxf(s_norm, EPSV);
}

// -------- 7. per-row contrastive loss. grid 196 x 256 thr --------
__global__ void k_loss() {
    const int i = blockIdx.x;
    const int tid = threadIdx.x;
    const int lane = tid & 31, w = tid >> 5;
    __shared__ float s_qi[DIM];
    __shared__ float s_row[NCLUST + 1];   // [0..195] row, [196] = pos (d_k)
    __shared__ float s_red[8];
    __shared__ float s_mx, s_sum;

    s_qi[tid] = g_centers[0][i * DIM + tid];
    __syncthreads();

    // each warp: dots for jj = w, w+8, ...; jj==196 means dot(q_i, k_i)
    for (int jj = w; jj <= NCLUST; jj += 8) {
        const float* vec = (jj == NCLUST) ? &g_centers[1][i * DIM]
                                          : &g_centers[0][jj * DIM];
        float p = 0.0f;
#pragma unroll
        for (int m = 0; m < 8; m++)
            p += s_qi[m * 32 + lane] * vec[m * 32 + lane];
#pragma unroll
        for (int off = 16; off > 0; off >>= 1)
            p += __shfl_xor_sync(0xFFFFFFFFu, p, off);
        if (lane == 0) s_row[jj] = p * TEMP_INV;
    }
    __syncthreads();

    // mask: diag <- d_k; empty columns <- -10
    if (tid < NCLUST) {
        float r = (tid == i) ? s_row[NCLUST] : s_row[tid];
        if (g_counts[tid] == 0) r = -10.0f;
        s_row[tid] = r;
    }
    __syncthreads();

    // block max over 196
    float v = (tid < NCLUST) ? s_row[tid] : -1e30f;
#pragma unroll
    for (int off = 16; off > 0; off >>= 1)
        v = fmaxf(v, __shfl_xor_sync(0xFFFFFFFFu, v, off));
    if (lane == 0) s_red[w] = v;
    __syncthreads();
    if (tid == 0) {
        float mx = s_red[0];
        for (int k = 1; k < 8; k++) mx = fmaxf(mx, s_red[k]);
        s_mx = mx;
    }
    __syncthreads();
    float mx = s_mx;

    float e = (tid < NCLUST) ? __expf(s_row[tid] - mx) : 0.0f;
#pragma unroll
    for (int off = 16; off > 0; off >>= 1)
        e += __shfl_xor_sync(0xFFFFFFFFu, e, off);
    if (lane == 0) s_red[w] = e;
    __syncthreads();
    if (tid == 0) {
        float tot = 0.0f;
        for (int k = 0; k < 8; k++) tot += s_red[k];
        s_sum = tot;
    }
    __syncthreads();

    if (tid == 0) {
        if (g_counts[i] == 0)
            g_loss[i] = 0.0f;
        else
            g_loss[i] = -s_row[i] + mx + logf(s_sum);
    }
}

// -------- 8. final reduce: mean over non-empty clusters --------
__global__ void k_final(float* out) {
    const int tid = threadIdx.x;
    const int lane = tid & 31, w = tid >> 5;
    float v = (tid < NCLUST) ? g_loss[tid] : 0.0f;
    float z = (tid < NCLUST && g_counts[tid] == 0) ? 1.0f : 0.0f;
#pragma unroll
    for (int off = 16; off > 0; off >>= 1) {
        v += __shfl_xor_sync(0xFFFFFFFFu, v, off);
        z += __shfl_xor_sync(0xFFFFFFFFu, z, off);
    }
    __shared__ float sv[8], sz[8];
    if (lane == 0) { sv[w] = v; sz[w] = z; }
    __syncthreads();
    if (tid == 0) {
        float tv = 0.0f, tz = 0.0f;
        for (int k = 0; k < 8; k++) { tv += sv[k]; tz += sz[k]; }
        out[0] = tv / ((float)NCLUST - tz);
    }
}

extern "C" void kernel_launch(void* const* d_in, const int* in_sizes, int n_in,
                              void* d_out, int out_size) {
    const float* im_q = (const float*)d_in[0];
    const float* im_k = (const float*)d_in[1];
    const int* labels = (const int*)d_in[2];
    float* out = (float*)d_out;

    k_zero<<<64, 256>>>();
    k_hist<<<256, 256>>>(labels);
    k_scan<<<1, 32>>>();
    k_scatter<<<256, 256>>>(labels);
    dim3 g5(NROWS / 256, 2);
    k_segsum<<<g5, 256>>>(im_q, im_k);
    dim3 g6(NCLUST, 2);
    k_centers<<<g6, 256>>>();
    k_loss<<<NCLUST, 256>>>();
    k_final<<<1, 256>>>(out);
}